// round 11
// baseline (speedup 1.0000x reference)
#include <cuda_runtime.h>
#include <cuda_bf16.h>
#include <math.h>
#include <stdint.h>

#define BATCH 16
#define CCH   256
#define NTOK  1024
#define NN    (1024*1024)
#define NHEAD 8
#define HID   1024
#define MTOT  (BATCH*NTOK)   // 16384

#define LOG2E    1.4426950408889634f
#define QSCALE   0.25504338f     // 32^-0.5 * log2(e)

// ---------------- helpers ----------------
__device__ __forceinline__ void mma16b(float c[4], uint32_t a0, uint32_t a1,
                                       uint32_t a2, uint32_t a3,
                                       uint32_t b0, uint32_t b1) {
    asm("mma.sync.aligned.m16n8k16.row.col.f32.bf16.bf16.f32 "
        "{%0,%1,%2,%3}, {%4,%5,%6,%7}, {%8,%9}, {%0,%1,%2,%3};"
        : "+f"(c[0]), "+f"(c[1]), "+f"(c[2]), "+f"(c[3])
        : "r"(a0), "r"(a1), "r"(a2), "r"(a3), "r"(b0), "r"(b1));
}
__device__ __forceinline__ uint32_t bf16pk(float lo, float hi) {
    uint32_t r;
    asm("cvt.rn.bf16x2.f32 %0, %1, %2;" : "=r"(r) : "f"(hi), "f"(lo));
    return r;
}
__device__ __forceinline__ float2 upbf(uint32_t u) {
    float2 r;
    r.x = __uint_as_float(u << 16);
    r.y = __uint_as_float(u & 0xffff0000u);
    return r;
}
__device__ __forceinline__ float ex2f(float x) {
    float r; asm("ex2.approx.ftz.f32 %0, %1;" : "=f"(r) : "f"(x)); return r;
}
__device__ __forceinline__ void cpa16(uint32_t dst, const void* src) {
    asm volatile("cp.async.cg.shared.global [%0], [%1], 16;"
                 :: "r"(dst), "l"(src) : "memory");
}
#define CPC()  asm volatile("cp.async.commit_group;" ::: "memory")
#define CPW1() asm volatile("cp.async.wait_group 1;" ::: "memory")
#define CPW0() asm volatile("cp.async.wait_group 0;" ::: "memory")

// ---------------- scratch ----------------
__device__ uint32_t g_x1b [MTOT*128];
__device__ uint32_t g_qb  [MTOT*128];        // Q bf16x2, pre-scaled by QSCALE
__device__ uint32_t g_kb  [MTOT*128];
__device__ uint32_t g_vt  [BATCH*NHEAD*32*512]; // V bf16x2 [b,h,d][tokpair]
__device__ uint32_t g_ob  [MTOT*128];
__device__ uint32_t g_biasb[NHEAD*NN/2];     // bf16x2 bias*log2e
__device__ float    g_x3  [MTOT*CCH];
__device__ uint32_t g_x4b [MTOT*128];
__device__ uint32_t g_ffnb[MTOT*512];
__device__ uint32_t g_wqkv[128*768];
__device__ uint32_t g_wprj[128*256];
__device__ uint32_t g_w1p [128*HID];
__device__ uint32_t g_w2p [512*256];

// ---------------- prep: weight converts + bias expand (merged) -------------
__global__ void __launch_bounds__(256) prep_k(
    const float* __restrict__ w0, const float* __restrict__ w1,
    const float* __restrict__ w2, const float* __restrict__ w3,
    uint32_t* __restrict__ o0, uint32_t* __restrict__ o1,
    uint32_t* __restrict__ o2, uint32_t* __restrict__ o3,
    const float* __restrict__ table, const int* __restrict__ relidx,
    uint32_t* __restrict__ biasB)
{
    int bid = blockIdx.x;
    if (bid < 1536) {
        int i = bid * 256 + threadIdx.x;
        const float* w; uint32_t* o; int N, li;
        if (i < 98304)       { w = w0; o = o0; N = 768;  li = i; }
        else if (i < 131072) { w = w1; o = o1; N = 256;  li = i - 98304; }
        else if (i < 262144) { w = w2; o = o2; N = 1024; li = i - 131072; }
        else                 { w = w3; o = o3; N = 256;  li = i - 262144; }
        int k2 = li / N, n = li - k2 * N;
        o[li] = bf16pk(w[(size_t)(2 * k2) * N + n],
                       w[(size_t)(2 * k2 + 1) * N + n]);
    } else {
        int t = (bid - 1536) * 256 + threadIdx.x;    // pair index
        int i0 = relidx[2 * t], i1 = relidx[2 * t + 1];
        #pragma unroll
        for (int h = 0; h < NHEAD; h++)
            biasB[(size_t)h * (NN / 2) + t] =
                bf16pk(table[i0 * NHEAD + h] * LOG2E,
                       table[i1 * NHEAD + h] * LOG2E);
    }
}

// ---------------- LN1: coalesced bchw read via smem transpose, bf16 out ----
__global__ void __launch_bounds__(256) ln1t_k(
    const float* __restrict__ x, const float* __restrict__ w,
    const float* __restrict__ bsh, uint32_t* __restrict__ outb)
{
    __shared__ float sm[256][33];
    __shared__ float red[8][32];
    __shared__ float musm[32], rssm[32];
    const int bb = blockIdx.y, p0 = blockIdx.x * 32;
    const int tid = threadIdx.x;

    #pragma unroll
    for (int pass = 0; pass < 8; pass++) {
        int idx = pass * 256 + tid;
        int c = idx >> 3, f = (idx & 7) * 4;
        float4 v = *(const float4*)&x[((size_t)(bb * 256 + c) << 10) + p0 + f];
        sm[c][f] = v.x; sm[c][f + 1] = v.y; sm[c][f + 2] = v.z; sm[c][f + 3] = v.w;
    }
    __syncthreads();
    const int p = tid & 31, sub = tid >> 5;
    float s = 0.0f;
    #pragma unroll
    for (int i = 0; i < 32; i++) s += sm[sub * 32 + i][p];
    red[sub][p] = s;
    __syncthreads();
    if (sub == 0) {
        float m = 0.0f;
        #pragma unroll
        for (int i = 0; i < 8; i++) m += red[i][p];
        musm[p] = m * (1.0f / 256.0f);
    }
    __syncthreads();
    float mu = musm[p], vs = 0.0f;
    #pragma unroll
    for (int i = 0; i < 32; i++) {
        float d = sm[sub * 32 + i][p] - mu;
        vs += d * d;
    }
    red[sub][p] = vs;
    __syncthreads();
    if (sub == 0) {
        float m = 0.0f;
        #pragma unroll
        for (int i = 0; i < 8; i++) m += red[i][p];
        rssm[p] = rsqrtf(m * (1.0f / 256.0f) + 1e-5f);
    }
    __syncthreads();
    const int tk = tid >> 3, ch = (tid & 7) * 32;
    const float mu2 = musm[tk], rs = rssm[tk];
    #pragma unroll
    for (int i = 0; i < 8; i++) {
        int c = ch + i * 4;
        float o0 = (sm[c][tk]     - mu2) * rs * w[c]     + bsh[c];
        float o1 = (sm[c + 1][tk] - mu2) * rs * w[c + 1] + bsh[c + 1];
        float o2 = (sm[c + 2][tk] - mu2) * rs * w[c + 2] + bsh[c + 2];
        float o3 = (sm[c + 3][tk] - mu2) * rs * w[c + 3] + bsh[c + 3];
        *(uint2*)&outb[(size_t)(bb * 1024 + p0 + tk) * 128 + c / 2] =
            make_uint2(bf16pk(o0, o1), bf16pk(o2, o3));
    }
}

// ---------------- LN2: warp per token, bf16 out ----------------
__global__ void __launch_bounds__(256) ln2w_k(
    const float* __restrict__ in, const float* __restrict__ w,
    const float* __restrict__ bsh, uint32_t* __restrict__ outb)
{
    const int token = blockIdx.x * 8 + (threadIdx.x >> 5);
    const int lane = threadIdx.x & 31;
    const float4* p = (const float4*)(in + (size_t)token * CCH);
    float4 a = p[lane], b = p[lane + 32];
    float s = a.x + a.y + a.z + a.w + b.x + b.y + b.z + b.w;
    #pragma unroll
    for (int o = 16; o; o >>= 1) s += __shfl_xor_sync(0xffffffffu, s, o);
    float mu = s * (1.0f / 256.0f);
    float v = 0.0f;
    #pragma unroll
    for (int e = 0; e < 4; e++) {
        float d0 = ((&a.x)[e] - mu), d1 = ((&b.x)[e] - mu);
        v += d0 * d0 + d1 * d1;
    }
    #pragma unroll
    for (int o = 16; o; o >>= 1) v += __shfl_xor_sync(0xffffffffu, v, o);
    float rs = rsqrtf(v * (1.0f / 256.0f) + 1e-5f);
    float4 wa = ((const float4*)w)[lane],   wb = ((const float4*)w)[lane + 32];
    float4 ba = ((const float4*)bsh)[lane], bb = ((const float4*)bsh)[lane + 32];
    float r0 = (a.x - mu) * rs * wa.x + ba.x;
    float r1 = (a.y - mu) * rs * wa.y + ba.y;
    float r2 = (a.z - mu) * rs * wa.z + ba.z;
    float r3 = (a.w - mu) * rs * wa.w + ba.w;
    float r4 = (b.x - mu) * rs * wb.x + bb.x;
    float r5 = (b.y - mu) * rs * wb.y + bb.y;
    float r6 = (b.z - mu) * rs * wb.z + bb.z;
    float r7 = (b.w - mu) * rs * wb.w + bb.w;
    uint32_t* op = outb + (size_t)token * 128;
    *(uint2*)(op + 2 * lane)      = make_uint2(bf16pk(r0, r1), bf16pk(r2, r3));
    *(uint2*)(op + 64 + 2 * lane) = make_uint2(bf16pk(r4, r5), bf16pk(r6, r7));
}

// ---------------- unified bf16 GEMM m16n8k16, cp.async 3-stage ----------------
// dyn smem: As 3*128*20 + Bs 3*16*136 = 14208 words (56832 B)
// EPI 0: gelu(acc+bias)->bf16x2. EPI 1: acc+bias+x3->bchw fp32.
// EPI 2: qkv split; Q scaled by QSCALE; V staged->transposed->g_vt.
// EPI 3: acc+bias+x(bchw)->fp32 row-major.
template<int EPI>
__global__ void __launch_bounds__(256, 2) gemm_b_k(
    const uint32_t* __restrict__ Ab, const uint32_t* __restrict__ Bp,
    const float* __restrict__ bias, void* __restrict__ Cv,
    int M, int N, int K,
    const float* __restrict__ aux,
    uint32_t* __restrict__ qb, uint32_t* __restrict__ kb,
    uint32_t* __restrict__ vt)
{
    extern __shared__ uint32_t dyn[];
    const int tid  = threadIdx.x;
    const int w    = tid >> 5;
    const int lane = tid & 31;
    const int g    = lane >> 2;
    const int t    = lane & 3;
    const int wm   = w >> 1;
    const int wn   = w & 1;
    const int row0 = blockIdx.y * 128;
    const int col0 = blockIdx.x * 128;
    const int K2   = K / 2;

    const uint32_t smb = (uint32_t)__cvta_generic_to_shared(dyn);

    float acc[2][8][4] = {};

    auto loadT = [&](int k0, int s) {
        #pragma unroll
        for (int p = 0; p < 2; p++) {
            int idx = p * 256 + tid;
            int m = idx >> 2, kq = (idx & 3) * 4;
            cpa16(smb + (uint32_t)(s * 2560 + m * 20 + kq) * 4,
                  Ab + (size_t)(row0 + m) * K2 + k0 / 2 + kq);
        }
        #pragma unroll
        for (int p = 0; p < 2; p++) {
            int idx = p * 256 + tid;
            int kk = idx >> 5, nq = (idx & 31) * 4;
            cpa16(smb + (uint32_t)(7680 + s * 2176 + kk * 136 + nq) * 4,
                  Bp + (size_t)(k0 / 2 + kk) * N + col0 + nq);
        }
    };

    const int nk = K / 32;
    loadT(0, 0); CPC();
    loadT(32, 1); CPC();

    for (int kt = 0; kt < nk; kt++) {
        int s = kt % 3;
        if (kt < nk - 1) { CPW1(); } else { CPW0(); }
        __syncthreads();
        if (kt + 2 < nk) { loadT((kt + 2) * 32, (kt + 2) % 3); CPC(); }
        const uint32_t* as = dyn + s * 2560;
        const uint32_t* bs = dyn + 7680 + s * 2176;
        #pragma unroll
        for (int j = 0; j < 2; j++) {
            int kw = j * 8;
            uint32_t a[2][4];
            #pragma unroll
            for (int mf = 0; mf < 2; mf++) {
                int mr = wm * 32 + mf * 16 + g;
                a[mf][0] = as[mr * 20 + kw + t];
                a[mf][1] = as[(mr + 8) * 20 + kw + t];
                a[mf][2] = as[mr * 20 + kw + t + 4];
                a[mf][3] = as[(mr + 8) * 20 + kw + t + 4];
            }
            #pragma unroll
            for (int nf = 0; nf < 8; nf++) {
                int nc = wn * 64 + nf * 8 + g;
                uint32_t b0 = bs[(j * 8 + t) * 136 + nc];
                uint32_t b1 = bs[(j * 8 + t + 4) * 136 + nc];
                mma16b(acc[0][nf], a[0][0], a[0][1], a[0][2], a[0][3], b0, b1);
                mma16b(acc[1][nf], a[1][0], a[1][1], a[1][2], a[1][3], b0, b1);
            }
        }
    }

    if (EPI == 2) __syncthreads();   // about to reuse dyn as V staging

    #pragma unroll
    for (int mf = 0; mf < 2; mf++) {
        #pragma unroll
        for (int nf = 0; nf < 8; nf++) {
            int n2 = col0 + wn * 64 + nf * 8 + 2 * t;
            #pragma unroll
            for (int half = 0; half < 2; half++) {
                int m = row0 + wm * 32 + mf * 16 + g + (half ? 8 : 0);
                float v0 = acc[mf][nf][2 * half];
                float v1 = acc[mf][nf][2 * half + 1];
                if (EPI == 0) {
                    v0 += bias[n2];
                    v1 += bias[n2 + 1];
                    v0 = 0.5f * v0 * (1.0f + erff(v0 * 0.7071067811865475f));
                    v1 = 0.5f * v1 * (1.0f + erff(v1 * 0.7071067811865475f));
                    ((uint32_t*)Cv)[(size_t)m * (N / 2) + n2 / 2] = bf16pk(v0, v1);
                } else if (EPI == 1) {
                    int bb2 = m >> 10, p = m & 1023;
                    v0 += bias[n2]     + aux[(size_t)m * CCH + n2];
                    v1 += bias[n2 + 1] + aux[(size_t)m * CCH + n2 + 1];
                    float* o = (float*)Cv;
                    o[((size_t)bb2 * CCH + n2)     * NTOK + p] = v0;
                    o[((size_t)bb2 * CCH + n2 + 1) * NTOK + p] = v1;
                } else if (EPI == 2) {
                    if (n2 < 256) {
                        qb[(size_t)m * 128 + n2 / 2] =
                            bf16pk(v0 * QSCALE, v1 * QSCALE);
                    } else if (n2 < 512) {
                        kb[(size_t)m * 128 + (n2 - 256) / 2] = bf16pk(v0, v1);
                    } else {
                        dyn[(m - row0) * 65 + (n2 - col0) / 2] = bf16pk(v0, v1);
                    }
                } else {
                    int bb2 = m >> 10, p = m & 1023;
                    v0 += bias[n2]     + aux[(((size_t)bb2 * CCH + n2) << 10) + p];
                    v1 += bias[n2 + 1] + aux[(((size_t)bb2 * CCH + n2 + 1) << 10) + p];
                    float* o = (float*)Cv;
                    o[(size_t)m * CCH + n2]     = v0;
                    o[(size_t)m * CCH + n2 + 1] = v1;
                }
            }
        }
    }

    // V transpose-pack: staged [128 tok][64 dp words] -> g_vt [b,h,d][tokpair]
    if (EPI == 2 && col0 >= 512) {
        __syncthreads();
        const int b = row0 >> 10;
        const int tp0 = (row0 & 1023) >> 1;
        #pragma unroll
        for (int it = 0; it < 16; it++) {
            int idx = it * 256 + tid;
            int dp = idx >> 6, tp = idx & 63;
            uint32_t w0 = dyn[(2 * tp) * 65 + dp];
            uint32_t w1 = dyn[(2 * tp + 1) * 65 + dp];
            uint32_t even = __byte_perm(w0, w1, 0x5410);  // lo halves
            uint32_t odd  = __byte_perm(w0, w1, 0x7632);  // hi halves
            int gd = (col0 - 512) + 2 * dp;
            int h = gd >> 5, dl = gd & 31;
            uint32_t* dst = vt + ((size_t)(b * NHEAD + h) * 32 + dl) * 512 + tp0 + tp;
            dst[0]   = even;
            dst[512] = odd;
        }
    }
}

// ---------------- bf16 flash attention, bias in cp.async ring ----------------
__global__ void __launch_bounds__(256, 2) attn_k(
    const uint32_t* __restrict__ Qb, const uint32_t* __restrict__ Kb,
    const uint32_t* __restrict__ Vt, const uint32_t* __restrict__ biasB,
    uint32_t* __restrict__ outb)
{
    extern __shared__ uint32_t dyn[];
    uint32_t* Ks  = dyn;                 // 3840 words
    uint32_t* Vs  = dyn + 3840;          // 3456 words
    uint32_t* Bsm = dyn + 7296;          // 13824 words

    const int q0 = blockIdx.x * 128;
    const int h  = blockIdx.y;
    const int b  = blockIdx.z;
    const int tid = threadIdx.x;
    const int wid = tid >> 5, lane = tid & 31;
    const int g = lane >> 2, t = lane & 3;

    const uint32_t ksb = (uint32_t)__cvta_generic_to_shared(Ks);
    const uint32_t vsb = (uint32_t)__cvta_generic_to_shared(Vs);
    const uint32_t bsb = (uint32_t)__cvta_generic_to_shared(Bsm);

    auto ldkv = [&](int kt, int s) {
        {
            int m = tid >> 2, kqw = (tid & 3) * 4;
            cpa16(ksb + (uint32_t)(s * 1280 + m * 20 + kqw) * 4,
                  Kb + (size_t)(b * NTOK + kt * 64 + m) * 128 + h * 16 + kqw);
        }
        {
            int m = tid >> 3, q8 = (tid & 7) * 4;
            cpa16(vsb + (uint32_t)(s * 1152 + m * 36 + q8) * 4,
                  Vt + ((size_t)(b * NHEAD + h) * 32 + m) * 512 + kt * 32 + q8);
        }
        {
            int r = tid >> 1, w0 = (tid & 1) * 16;
            const uint32_t* src = biasB + (size_t)h * (NN / 2)
                                  + (size_t)(q0 + r) * 512 + kt * 32 + w0;
            #pragma unroll
            for (int i = 0; i < 4; i++)
                cpa16(bsb + (uint32_t)(s * 4608 + r * 36 + w0 + i * 4) * 4,
                      src + i * 4);
        }
    };

    ldkv(0, 0); CPC();
    ldkv(1, 1); CPC();

    uint32_t qf[2][4];
    {
        const uint32_t* qp = Qb + (size_t)(b * NTOK + q0 + wid * 16) * 128 + h * 16;
        #pragma unroll
        for (int j = 0; j < 2; j++) {
            qf[j][0] = qp[(size_t)g * 128 + j * 8 + t];
            qf[j][1] = qp[(size_t)(g + 8) * 128 + j * 8 + t];
            qf[j][2] = qp[(size_t)g * 128 + j * 8 + 4 + t];
            qf[j][3] = qp[(size_t)(g + 8) * 128 + j * 8 + 4 + t];
        }
    }

    float o[4][4] = {};
    float l0 = 0.0f, l1 = 0.0f;

    for (int kt = 0; kt < 16; kt++) {
        int s = kt % 3;
        if (kt < 15) { CPW1(); } else { CPW0(); }
        __syncthreads();
        if (kt + 2 < 16) { ldkv(kt + 2, (kt + 2) % 3); CPC(); }
        const uint32_t* ks = Ks + s * 1280;
        const uint32_t* vs = Vs + s * 1152;
        const uint32_t* bsm = Bsm + s * 4608 + (wid * 16 + g) * 36;

        float c[8][4] = {};
        #pragma unroll
        for (int j = 0; j < 2; j++) {
            #pragma unroll
            for (int nf = 0; nf < 8; nf++) {
                int kc = nf * 8 + g;
                mma16b(c[nf], qf[j][0], qf[j][1], qf[j][2], qf[j][3],
                       ks[kc * 20 + j * 8 + t], ks[kc * 20 + j * 8 + 4 + t]);
            }
        }

        // softmax piece: Q pre-scaled, bias pre-scaled by log2e -> one ex2
        #pragma unroll
        for (int nf = 0; nf < 8; nf++) {
            float2 bA = upbf(bsm[nf * 4 + t]);
            float2 bB = upbf(bsm[288 + nf * 4 + t]);
            c[nf][0] = ex2f(c[nf][0] + bA.x);
            c[nf][1] = ex2f(c[nf][1] + bA.y);
            c[nf][2] = ex2f(c[nf][2] + bB.x);
            c[nf][3] = ex2f(c[nf][3] + bB.y);
            l0 += c[nf][0] + c[nf][1];
            l1 += c[nf][2] + c[nf][3];
        }

        #pragma unroll
        for (int j = 0; j < 4; j++) {
            uint32_t a0 = bf16pk(c[2 * j][0], c[2 * j][1]);
            uint32_t a1 = bf16pk(c[2 * j][2], c[2 * j][3]);
            uint32_t a2 = bf16pk(c[2 * j + 1][0], c[2 * j + 1][1]);
            uint32_t a3 = bf16pk(c[2 * j + 1][2], c[2 * j + 1][3]);
            #pragma unroll
            for (int dn = 0; dn < 4; dn++) {
                int vcb = (dn * 8 + g) * 36 + j * 8;
                mma16b(o[dn], a0, a1, a2, a3, vs[vcb + t], vs[vcb + 4 + t]);
            }
        }
    }

    l0 += __shfl_xor_sync(0xffffffffu, l0, 1);
    l0 += __shfl_xor_sync(0xffffffffu, l0, 2);
    l1 += __shfl_xor_sync(0xffffffffu, l1, 1);
    l1 += __shfl_xor_sync(0xffffffffu, l1, 2);

    float inv0 = 1.0f / l0, inv1 = 1.0f / l1;
    uint32_t* op = outb + (size_t)(b * NTOK + q0 + wid * 16 + g) * 128 + h * 16;
    #pragma unroll
    for (int dn = 0; dn < 4; dn++) {
        op[dn * 4 + t]           = bf16pk(o[dn][0] * inv0, o[dn][1] * inv0);
        op[8 * 128 + dn * 4 + t] = bf16pk(o[dn][2] * inv1, o[dn][3] * inv1);
    }
}

// ---------------- launch ----------------
extern "C" void kernel_launch(void* const* d_in, const int* in_sizes, int n_in,
                              void* d_out, int out_size)
{
    const float* x       = (const float*)d_in[0];
    const float* qkv_w   = (const float*)d_in[1];
    const float* proj_w  = (const float*)d_in[2];
    const float* proj_b  = (const float*)d_in[3];
    const float* ffn_w1  = (const float*)d_in[4];
    const float* ffn_b1  = (const float*)d_in[5];
    const float* ffn_w2  = (const float*)d_in[6];
    const float* ffn_b2  = (const float*)d_in[7];
    const float* n1w     = (const float*)d_in[8];
    const float* n1b     = (const float*)d_in[9];
    const float* n2w     = (const float*)d_in[10];
    const float* n2b     = (const float*)d_in[11];
    const float* table   = (const float*)d_in[12];
    const int*   relidx  = (const int*)d_in[13];
    float* out = (float*)d_out;

    void *px1b, *pqb, *pkb, *pvt, *pob, *pbiasb, *px3, *px4b, *pffnb;
    void *pwqkv, *pwprj, *pw1p, *pw2p;
    cudaGetSymbolAddress(&px1b,   g_x1b);
    cudaGetSymbolAddress(&pqb,    g_qb);
    cudaGetSymbolAddress(&pkb,    g_kb);
    cudaGetSymbolAddress(&pvt,    g_vt);
    cudaGetSymbolAddress(&pob,    g_ob);
    cudaGetSymbolAddress(&pbiasb, g_biasb);
    cudaGetSymbolAddress(&px3,    g_x3);
    cudaGetSymbolAddress(&px4b,   g_x4b);
    cudaGetSymbolAddress(&pffnb,  g_ffnb);
    cudaGetSymbolAddress(&pwqkv,  g_wqkv);
    cudaGetSymbolAddress(&pwprj,  g_wprj);
    cudaGetSymbolAddress(&pw1p,   g_w1p);
    cudaGetSymbolAddress(&pw2p,   g_w2p);

    cudaFuncSetAttribute(attn_k, cudaFuncAttributeMaxDynamicSharedMemorySize,
                         84480);
    cudaFuncSetAttribute(gemm_b_k<0>, cudaFuncAttributeMaxDynamicSharedMemorySize, 56832);
    cudaFuncSetAttribute(gemm_b_k<1>, cudaFuncAttributeMaxDynamicSharedMemorySize, 56832);
    cudaFuncSetAttribute(gemm_b_k<2>, cudaFuncAttributeMaxDynamicSharedMemorySize, 56832);
    cudaFuncSetAttribute(gemm_b_k<3>, cudaFuncAttributeMaxDynamicSharedMemorySize, 56832);

    prep_k<<<3584, 256>>>(qkv_w, proj_w, ffn_w1, ffn_w2,
                          (uint32_t*)pwqkv, (uint32_t*)pwprj,
                          (uint32_t*)pw1p, (uint32_t*)pw2p,
                          table, relidx, (uint32_t*)pbiasb);
    ln1t_k<<<dim3(32, BATCH), 256>>>(x, n1w, n1b, (uint32_t*)px1b);
    gemm_b_k<2><<<dim3(6, 128), 256, 56832>>>(
        (const uint32_t*)px1b, (const uint32_t*)pwqkv, nullptr, nullptr,
        MTOT, 768, 256, nullptr,
        (uint32_t*)pqb, (uint32_t*)pkb, (uint32_t*)pvt);
    attn_k<<<dim3(NTOK / 128, NHEAD, BATCH), 256, 84480>>>(
        (const uint32_t*)pqb, (const uint32_t*)pkb, (const uint32_t*)pvt,
        (const uint32_t*)pbiasb, (uint32_t*)pob);
    gemm_b_k<3><<<dim3(2, 128), 256, 56832>>>(
        (const uint32_t*)pob, (const uint32_t*)pwprj, proj_b, px3,
        MTOT, 256, 256, x, nullptr, nullptr, nullptr);
    ln2w_k<<<MTOT / 8, 256>>>((const float*)px3, n2w, n2b, (uint32_t*)px4b);
    gemm_b_k<0><<<dim3(8, 128), 256, 56832>>>(
        (const uint32_t*)px4b, (const uint32_t*)pw1p, ffn_b1, pffnb,
        MTOT, HID, 256, nullptr, nullptr, nullptr, nullptr);
    gemm_b_k<1><<<dim3(2, 128), 256, 56832>>>(
        (const uint32_t*)pffnb, (const uint32_t*)pw2p, ffn_b2, out,
        MTOT, 256, 1024, (const float*)px3, nullptr, nullptr, nullptr);
}

// round 13
// speedup vs baseline: 1.4845x; 1.4845x over previous
#include <cuda_runtime.h>
#include <cuda_bf16.h>
#include <math.h>
#include <stdint.h>

#define BATCH 16
#define CCH   256
#define NTOK  1024
#define NN    (1024*1024)
#define NHEAD 8
#define HID   1024
#define MTOT  (BATCH*NTOK)   // 16384

#define LOG2E    1.4426950408889634f
#define QSCALE   0.25504338f     // 32^-0.5 * log2(e)

// ---------------- helpers ----------------
__device__ __forceinline__ void mma16b(float c[4], uint32_t a0, uint32_t a1,
                                       uint32_t a2, uint32_t a3,
                                       uint32_t b0, uint32_t b1) {
    asm("mma.sync.aligned.m16n8k16.row.col.f32.bf16.bf16.f32 "
        "{%0,%1,%2,%3}, {%4,%5,%6,%7}, {%8,%9}, {%0,%1,%2,%3};"
        : "+f"(c[0]), "+f"(c[1]), "+f"(c[2]), "+f"(c[3])
        : "r"(a0), "r"(a1), "r"(a2), "r"(a3), "r"(b0), "r"(b1));
}
__device__ __forceinline__ uint32_t bf16pk(float lo, float hi) {
    uint32_t r;
    asm("cvt.rn.bf16x2.f32 %0, %1, %2;" : "=r"(r) : "f"(hi), "f"(lo));
    return r;
}
__device__ __forceinline__ float2 upbf(uint32_t u) {
    float2 r;
    r.x = __uint_as_float(u << 16);
    r.y = __uint_as_float(u & 0xffff0000u);
    return r;
}
__device__ __forceinline__ float ex2f(float x) {
    float r; asm("ex2.approx.ftz.f32 %0, %1;" : "=f"(r) : "f"(x)); return r;
}
__device__ __forceinline__ void cpa16(uint32_t dst, const void* src) {
    asm volatile("cp.async.cg.shared.global [%0], [%1], 16;"
                 :: "r"(dst), "l"(src) : "memory");
}
#define CPC()  asm volatile("cp.async.commit_group;" ::: "memory")
#define CPW1() asm volatile("cp.async.wait_group 1;" ::: "memory")
#define CPW0() asm volatile("cp.async.wait_group 0;" ::: "memory")

// ---------------- scratch ----------------
__device__ uint32_t g_x1b [MTOT*128];
__device__ uint32_t g_qb  [MTOT*128];        // Q bf16x2, pre-scaled by QSCALE
__device__ uint32_t g_kb  [MTOT*128];
__device__ float    g_vf  [MTOT*CCH];
__device__ uint32_t g_vt  [BATCH*NHEAD*32*512];
__device__ uint32_t g_ob  [MTOT*128];
__device__ uint32_t g_biasb[NHEAD*NN/2];     // bf16x2 bias*log2e
__device__ float    g_x3  [MTOT*CCH];
__device__ uint32_t g_x4b [MTOT*128];
__device__ uint32_t g_ffnb[MTOT*512];
__device__ uint32_t g_wqkv[128*768];
__device__ uint32_t g_wprj[128*256];
__device__ uint32_t g_w1p [128*HID];
__device__ uint32_t g_w2p [512*256];

// ---------------- prep: weight converts + bias expand (merged) -------------
__global__ void __launch_bounds__(256) prep_k(
    const float* __restrict__ w0, const float* __restrict__ w1,
    const float* __restrict__ w2, const float* __restrict__ w3,
    uint32_t* __restrict__ o0, uint32_t* __restrict__ o1,
    uint32_t* __restrict__ o2, uint32_t* __restrict__ o3,
    const float* __restrict__ table, const int* __restrict__ relidx,
    uint32_t* __restrict__ biasB)
{
    int bid = blockIdx.x;
    if (bid < 1536) {
        int i = bid * 256 + threadIdx.x;
        const float* w; uint32_t* o; int N, li;
        if (i < 98304)       { w = w0; o = o0; N = 768;  li = i; }
        else if (i < 131072) { w = w1; o = o1; N = 256;  li = i - 98304; }
        else if (i < 262144) { w = w2; o = o2; N = 1024; li = i - 131072; }
        else                 { w = w3; o = o3; N = 256;  li = i - 262144; }
        int k2 = li / N, n = li - k2 * N;
        o[li] = bf16pk(w[(size_t)(2 * k2) * N + n],
                       w[(size_t)(2 * k2 + 1) * N + n]);
    } else {
        int t = (bid - 1536) * 256 + threadIdx.x;    // pair index
        int i0 = relidx[2 * t], i1 = relidx[2 * t + 1];
        #pragma unroll
        for (int h = 0; h < NHEAD; h++)
            biasB[(size_t)h * (NN / 2) + t] =
                bf16pk(table[i0 * NHEAD + h] * LOG2E,
                       table[i1 * NHEAD + h] * LOG2E);
    }
}

// ---------------- LN1: coalesced bchw read via smem transpose, bf16 out ----
__global__ void __launch_bounds__(256) ln1t_k(
    const float* __restrict__ x, const float* __restrict__ w,
    const float* __restrict__ bsh, uint32_t* __restrict__ outb)
{
    __shared__ float sm[256][33];
    __shared__ float red[8][32];
    __shared__ float musm[32], rssm[32];
    const int bb = blockIdx.y, p0 = blockIdx.x * 32;
    const int tid = threadIdx.x;

    #pragma unroll
    for (int pass = 0; pass < 8; pass++) {
        int idx = pass * 256 + tid;
        int c = idx >> 3, f = (idx & 7) * 4;
        float4 v = *(const float4*)&x[((size_t)(bb * 256 + c) << 10) + p0 + f];
        sm[c][f] = v.x; sm[c][f + 1] = v.y; sm[c][f + 2] = v.z; sm[c][f + 3] = v.w;
    }
    __syncthreads();
    const int p = tid & 31, sub = tid >> 5;
    float s = 0.0f;
    #pragma unroll
    for (int i = 0; i < 32; i++) s += sm[sub * 32 + i][p];
    red[sub][p] = s;
    __syncthreads();
    if (sub == 0) {
        float m = 0.0f;
        #pragma unroll
        for (int i = 0; i < 8; i++) m += red[i][p];
        musm[p] = m * (1.0f / 256.0f);
    }
    __syncthreads();
    float mu = musm[p], vs = 0.0f;
    #pragma unroll
    for (int i = 0; i < 32; i++) {
        float d = sm[sub * 32 + i][p] - mu;
        vs += d * d;
    }
    red[sub][p] = vs;
    __syncthreads();
    if (sub == 0) {
        float m = 0.0f;
        #pragma unroll
        for (int i = 0; i < 8; i++) m += red[i][p];
        rssm[p] = rsqrtf(m * (1.0f / 256.0f) + 1e-5f);
    }
    __syncthreads();
    const int tk = tid >> 3, ch = (tid & 7) * 32;
    const float mu2 = musm[tk], rs = rssm[tk];
    #pragma unroll
    for (int i = 0; i < 8; i++) {
        int c = ch + i * 4;
        float o0 = (sm[c][tk]     - mu2) * rs * w[c]     + bsh[c];
        float o1 = (sm[c + 1][tk] - mu2) * rs * w[c + 1] + bsh[c + 1];
        float o2 = (sm[c + 2][tk] - mu2) * rs * w[c + 2] + bsh[c + 2];
        float o3 = (sm[c + 3][tk] - mu2) * rs * w[c + 3] + bsh[c + 3];
        *(uint2*)&outb[(size_t)(bb * 1024 + p0 + tk) * 128 + c / 2] =
            make_uint2(bf16pk(o0, o1), bf16pk(o2, o3));
    }
}

// ---------------- LN2: warp per token, bf16 out ----------------
__global__ void __launch_bounds__(256) ln2w_k(
    const float* __restrict__ in, const float* __restrict__ w,
    const float* __restrict__ bsh, uint32_t* __restrict__ outb)
{
    const int token = blockIdx.x * 8 + (threadIdx.x >> 5);
    const int lane = threadIdx.x & 31;
    const float4* p = (const float4*)(in + (size_t)token * CCH);
    float4 a = p[lane], b = p[lane + 32];
    float s = a.x + a.y + a.z + a.w + b.x + b.y + b.z + b.w;
    #pragma unroll
    for (int o = 16; o; o >>= 1) s += __shfl_xor_sync(0xffffffffu, s, o);
    float mu = s * (1.0f / 256.0f);
    float v = 0.0f;
    #pragma unroll
    for (int e = 0; e < 4; e++) {
        float d0 = ((&a.x)[e] - mu), d1 = ((&b.x)[e] - mu);
        v += d0 * d0 + d1 * d1;
    }
    #pragma unroll
    for (int o = 16; o; o >>= 1) v += __shfl_xor_sync(0xffffffffu, v, o);
    float rs = rsqrtf(v * (1.0f / 256.0f) + 1e-5f);
    float4 wa = ((const float4*)w)[lane],   wb = ((const float4*)w)[lane + 32];
    float4 ba = ((const float4*)bsh)[lane], bb = ((const float4*)bsh)[lane + 32];
    float r0 = (a.x - mu) * rs * wa.x + ba.x;
    float r1 = (a.y - mu) * rs * wa.y + ba.y;
    float r2 = (a.z - mu) * rs * wa.z + ba.z;
    float r3 = (a.w - mu) * rs * wa.w + ba.w;
    float r4 = (b.x - mu) * rs * wb.x + bb.x;
    float r5 = (b.y - mu) * rs * wb.y + bb.y;
    float r6 = (b.z - mu) * rs * wb.z + bb.z;
    float r7 = (b.w - mu) * rs * wb.w + bb.w;
    uint32_t* op = outb + (size_t)token * 128;
    *(uint2*)(op + 2 * lane)      = make_uint2(bf16pk(r0, r1), bf16pk(r2, r3));
    *(uint2*)(op + 64 + 2 * lane) = make_uint2(bf16pk(r4, r5), bf16pk(r6, r7));
}

// ---------------- V transpose-pack ----------------
__global__ void __launch_bounds__(256) vt_cvt_k(
    const float* __restrict__ vf, uint32_t* __restrict__ vt)
{
    __shared__ float sm[128][33];
    const int tile = blockIdx.x, h = blockIdx.y, b = blockIdx.z;
    const int t0 = tile * 128;
    const int tid = threadIdx.x;
    #pragma unroll
    for (int pass = 0; pass < 4; pass++) {
        int idx = pass * 256 + tid;
        int tok = idx >> 3, f = (idx & 7) * 4;
        float4 v = *(const float4*)&vf[(size_t)(b * 1024 + t0 + tok) * 256
                                       + h * 32 + f];
        sm[tok][f] = v.x; sm[tok][f + 1] = v.y;
        sm[tok][f + 2] = v.z; sm[tok][f + 3] = v.w;
    }
    __syncthreads();
    const int d = tid >> 3, jb = (tid & 7) * 8;
    uint32_t wbuf[8];
    #pragma unroll
    for (int i = 0; i < 8; i++) {
        int j = jb + i;
        wbuf[i] = bf16pk(sm[2 * j][d], sm[2 * j + 1][d]);
    }
    uint32_t* dst = vt + ((size_t)(b * NHEAD + h) * 32 + d) * 512 + tile * 64 + jb;
    *(uint4*)dst       = make_uint4(wbuf[0], wbuf[1], wbuf[2], wbuf[3]);
    *(uint4*)(dst + 4) = make_uint4(wbuf[4], wbuf[5], wbuf[6], wbuf[7]);
}

// ---------------- unified bf16 GEMM m16n8k16, cp.async 2-stage (R10) --------
template<int EPI>
__global__ void __launch_bounds__(256, 2) gemm_b_k(
    const uint32_t* __restrict__ Ab, const uint32_t* __restrict__ Bp,
    const float* __restrict__ bias, void* __restrict__ Cv,
    int M, int N, int K,
    const float* __restrict__ aux,
    uint32_t* __restrict__ qb, uint32_t* __restrict__ kb,
    float* __restrict__ vf)
{
    __shared__ uint32_t As[2 * 128 * 20];
    __shared__ uint32_t Bs[2 * 16 * 136];

    const int tid  = threadIdx.x;
    const int w    = tid >> 5;
    const int lane = tid & 31;
    const int g    = lane >> 2;
    const int t    = lane & 3;
    const int wm   = w >> 1;
    const int wn   = w & 1;
    const int row0 = blockIdx.y * 128;
    const int col0 = blockIdx.x * 128;
    const int K2   = K / 2;

    const uint32_t asb = (uint32_t)__cvta_generic_to_shared(As);
    const uint32_t bsb = (uint32_t)__cvta_generic_to_shared(Bs);

    float acc[2][8][4] = {};

    auto loadT = [&](int k0, int s) {
        #pragma unroll
        for (int p = 0; p < 2; p++) {
            int idx = p * 256 + tid;
            int m = idx >> 2, kq = (idx & 3) * 4;
            cpa16(asb + (uint32_t)(s * 2560 + m * 20 + kq) * 4,
                  Ab + (size_t)(row0 + m) * K2 + k0 / 2 + kq);
        }
        #pragma unroll
        for (int p = 0; p < 2; p++) {
            int idx = p * 256 + tid;
            int kk = idx >> 5, nq = (idx & 31) * 4;
            cpa16(bsb + (uint32_t)(s * 2176 + kk * 136 + nq) * 4,
                  Bp + (size_t)(k0 / 2 + kk) * N + col0 + nq);
        }
    };

    const int nk = K / 32;
    loadT(0, 0); CPC();

    for (int kt = 0; kt < nk; kt++) {
        int s = kt & 1;
        if (kt + 1 < nk) loadT((kt + 1) * 32, s ^ 1);
        CPC(); CPW1();
        __syncthreads();
        const uint32_t* as = As + s * 2560;
        const uint32_t* bs = Bs + s * 2176;
        #pragma unroll
        for (int j = 0; j < 2; j++) {
            int kw = j * 8;
            uint32_t a[2][4];
            #pragma unroll
            for (int mf = 0; mf < 2; mf++) {
                int mr = wm * 32 + mf * 16 + g;
                a[mf][0] = as[mr * 20 + kw + t];
                a[mf][1] = as[(mr + 8) * 20 + kw + t];
                a[mf][2] = as[mr * 20 + kw + t + 4];
                a[mf][3] = as[(mr + 8) * 20 + kw + t + 4];
            }
            #pragma unroll
            for (int nf = 0; nf < 8; nf++) {
                int nc = wn * 64 + nf * 8 + g;
                uint32_t b0 = bs[(j * 8 + t) * 136 + nc];
                uint32_t b1 = bs[(j * 8 + t + 4) * 136 + nc];
                mma16b(acc[0][nf], a[0][0], a[0][1], a[0][2], a[0][3], b0, b1);
                mma16b(acc[1][nf], a[1][0], a[1][1], a[1][2], a[1][3], b0, b1);
            }
        }
        __syncthreads();
    }

    #pragma unroll
    for (int mf = 0; mf < 2; mf++) {
        #pragma unroll
        for (int nf = 0; nf < 8; nf++) {
            int n2 = col0 + wn * 64 + nf * 8 + 2 * t;
            #pragma unroll
            for (int half = 0; half < 2; half++) {
                int m = row0 + wm * 32 + mf * 16 + g + (half ? 8 : 0);
                float v0 = acc[mf][nf][2 * half];
                float v1 = acc[mf][nf][2 * half + 1];
                if (EPI == 0) {
                    v0 += bias[n2];
                    v1 += bias[n2 + 1];
                    v0 = 0.5f * v0 * (1.0f + erff(v0 * 0.7071067811865475f));
                    v1 = 0.5f * v1 * (1.0f + erff(v1 * 0.7071067811865475f));
                    ((uint32_t*)Cv)[(size_t)m * (N / 2) + n2 / 2] = bf16pk(v0, v1);
                } else if (EPI == 1) {
                    int bb2 = m >> 10, p = m & 1023;
                    v0 += bias[n2]     + aux[(size_t)m * CCH + n2];
                    v1 += bias[n2 + 1] + aux[(size_t)m * CCH + n2 + 1];
                    float* o = (float*)Cv;
                    o[((size_t)bb2 * CCH + n2)     * NTOK + p] = v0;
                    o[((size_t)bb2 * CCH + n2 + 1) * NTOK + p] = v1;
                } else if (EPI == 2) {
                    if (n2 < 256) {
                        qb[(size_t)m * 128 + n2 / 2] =
                            bf16pk(v0 * QSCALE, v1 * QSCALE);
                    } else if (n2 < 512) {
                        kb[(size_t)m * 128 + (n2 - 256) / 2] = bf16pk(v0, v1);
                    } else {
                        vf[(size_t)m * 256 + (n2 - 512)]     = v0;
                        vf[(size_t)m * 256 + (n2 - 512) + 1] = v1;
                    }
                } else {
                    int bb2 = m >> 10, p = m & 1023;
                    v0 += bias[n2]     + aux[(((size_t)bb2 * CCH + n2) << 10) + p];
                    v1 += bias[n2 + 1] + aux[(((size_t)bb2 * CCH + n2 + 1) << 10) + p];
                    float* o = (float*)Cv;
                    o[(size_t)m * CCH + n2]     = v0;
                    o[(size_t)m * CCH + n2 + 1] = v1;
                }
            }
        }
    }
}

// ---------------- bf16 flash attention, bias ring + ex2 softmax -------------
__global__ void __launch_bounds__(256, 2) attn_k(
    const uint32_t* __restrict__ Qb, const uint32_t* __restrict__ Kb,
    const uint32_t* __restrict__ Vt, const uint32_t* __restrict__ biasB,
    uint32_t* __restrict__ outb)
{
    extern __shared__ uint32_t dyn[];
    uint32_t* Ks  = dyn;                 // 3840 words
    uint32_t* Vs  = dyn + 3840;          // 3456 words
    uint32_t* Bsm = dyn + 7296;          // 13824 words

    const int q0 = blockIdx.x * 128;
    const int h  = blockIdx.y;
    const int b  = blockIdx.z;
    const int tid = threadIdx.x;
    const int wid = tid >> 5, lane = tid & 31;
    const int g = lane >> 2, t = lane & 3;

    const uint32_t ksb = (uint32_t)__cvta_generic_to_shared(Ks);
    const uint32_t vsb = (uint32_t)__cvta_generic_to_shared(Vs);
    const uint32_t bsb = (uint32_t)__cvta_generic_to_shared(Bsm);

    auto ldkv = [&](int kt, int s) {
        {
            int m = tid >> 2, kqw = (tid & 3) * 4;
            cpa16(ksb + (uint32_t)(s * 1280 + m * 20 + kqw) * 4,
                  Kb + (size_t)(b * NTOK + kt * 64 + m) * 128 + h * 16 + kqw);
        }
        {
            int m = tid >> 3, q8 = (tid & 7) * 4;
            cpa16(vsb + (uint32_t)(s * 1152 + m * 36 + q8) * 4,
                  Vt + ((size_t)(b * NHEAD + h) * 32 + m) * 512 + kt * 32 + q8);
        }
        {
            int r = tid >> 1, w0 = (tid & 1) * 16;
            const uint32_t* src = biasB + (size_t)h * (NN / 2)
                                  + (size_t)(q0 + r) * 512 + kt * 32 + w0;
            #pragma unroll
            for (int i = 0; i < 4; i++)
                cpa16(bsb + (uint32_t)(s * 4608 + r * 36 + w0 + i * 4) * 4,
                      src + i * 4);
        }
    };

    ldkv(0, 0); CPC();
    ldkv(1, 1); CPC();

    uint32_t qf[2][4];
    {
        const uint32_t* qp = Qb + (size_t)(b * NTOK + q0 + wid * 16) * 128 + h * 16;
        #pragma unroll
        for (int j = 0; j < 2; j++) {
            qf[j][0] = qp[(size_t)g * 128 + j * 8 + t];
            qf[j][1] = qp[(size_t)(g + 8) * 128 + j * 8 + t];
            qf[j][2] = qp[(size_t)g * 128 + j * 8 + 4 + t];
            qf[j][3] = qp[(size_t)(g + 8) * 128 + j * 8 + 4 + t];
        }
    }

    float o[4][4] = {};
    float l0 = 0.0f, l1 = 0.0f;

    for (int kt = 0; kt < 16; kt++) {
        int s = kt % 3;
        if (kt < 15) { CPW1(); } else { CPW0(); }
        __syncthreads();
        if (kt + 2 < 16) { ldkv(kt + 2, (kt + 2) % 3); CPC(); }
        const uint32_t* ks = Ks + s * 1280;
        const uint32_t* vs = Vs + s * 1152;
        const uint32_t* bsm = Bsm + s * 4608 + (wid * 16 + g) * 36;

        float c[8][4] = {};
        #pragma unroll
        for (int j = 0; j < 2; j++) {
            #pragma unroll
            for (int nf = 0; nf < 8; nf++) {
                int kc = nf * 8 + g;
                mma16b(c[nf], qf[j][0], qf[j][1], qf[j][2], qf[j][3],
                       ks[kc * 20 + j * 8 + t], ks[kc * 20 + j * 8 + 4 + t]);
            }
        }

        // softmax piece: Q pre-scaled, bias pre-scaled by log2e -> one ex2
        #pragma unroll
        for (int nf = 0; nf < 8; nf++) {
            float2 bA = upbf(bsm[nf * 4 + t]);
            float2 bB = upbf(bsm[288 + nf * 4 + t]);
            c[nf][0] = ex2f(c[nf][0] + bA.x);
            c[nf][1] = ex2f(c[nf][1] + bA.y);
            c[nf][2] = ex2f(c[nf][2] + bB.x);
            c[nf][3] = ex2f(c[nf][3] + bB.y);
            l0 += c[nf][0] + c[nf][1];
            l1 += c[nf][2] + c[nf][3];
        }

        #pragma unroll
        for (int j = 0; j < 4; j++) {
            uint32_t a0 = bf16pk(c[2 * j][0], c[2 * j][1]);
            uint32_t a1 = bf16pk(c[2 * j][2], c[2 * j][3]);
            uint32_t a2 = bf16pk(c[2 * j + 1][0], c[2 * j + 1][1]);
            uint32_t a3 = bf16pk(c[2 * j + 1][2], c[2 * j + 1][3]);
            #pragma unroll
            for (int dn = 0; dn < 4; dn++) {
                int vcb = (dn * 8 + g) * 36 + j * 8;
                mma16b(o[dn], a0, a1, a2, a3, vs[vcb + t], vs[vcb + 4 + t]);
            }
        }
    }

    l0 += __shfl_xor_sync(0xffffffffu, l0, 1);
    l0 += __shfl_xor_sync(0xffffffffu, l0, 2);
    l1 += __shfl_xor_sync(0xffffffffu, l1, 1);
    l1 += __shfl_xor_sync(0xffffffffu, l1, 2);

    float inv0 = 1.0f / l0, inv1 = 1.0f / l1;
    uint32_t* op = outb + (size_t)(b * NTOK + q0 + wid * 16 + g) * 128 + h * 16;
    #pragma unroll
    for (int dn = 0; dn < 4; dn++) {
        op[dn * 4 + t]           = bf16pk(o[dn][0] * inv0, o[dn][1] * inv0);
        op[8 * 128 + dn * 4 + t] = bf16pk(o[dn][2] * inv1, o[dn][3] * inv1);
    }
}

// ---------------- launch ----------------
extern "C" void kernel_launch(void* const* d_in, const int* in_sizes, int n_in,
                              void* d_out, int out_size)
{
    const float* x       = (const float*)d_in[0];
    const float* qkv_w   = (const float*)d_in[1];
    const float* proj_w  = (const float*)d_in[2];
    const float* proj_b  = (const float*)d_in[3];
    const float* ffn_w1  = (const float*)d_in[4];
    const float* ffn_b1  = (const float*)d_in[5];
    const float* ffn_w2  = (const float*)d_in[6];
    const float* ffn_b2  = (const float*)d_in[7];
    const float* n1w     = (const float*)d_in[8];
    const float* n1b     = (const float*)d_in[9];
    const float* n2w     = (const float*)d_in[10];
    const float* n2b     = (const float*)d_in[11];
    const float* table   = (const float*)d_in[12];
    const int*   relidx  = (const int*)d_in[13];
    float* out = (float*)d_out;

    void *px1b, *pqb, *pkb, *pvf, *pvt, *pob, *pbiasb, *px3, *px4b, *pffnb;
    void *pwqkv, *pwprj, *pw1p, *pw2p;
    cudaGetSymbolAddress(&px1b,   g_x1b);
    cudaGetSymbolAddress(&pqb,    g_qb);
    cudaGetSymbolAddress(&pkb,    g_kb);
    cudaGetSymbolAddress(&pvf,    g_vf);
    cudaGetSymbolAddress(&pvt,    g_vt);
    cudaGetSymbolAddress(&pob,    g_ob);
    cudaGetSymbolAddress(&pbiasb, g_biasb);
    cudaGetSymbolAddress(&px3,    g_x3);
    cudaGetSymbolAddress(&px4b,   g_x4b);
    cudaGetSymbolAddress(&pffnb,  g_ffnb);
    cudaGetSymbolAddress(&pwqkv,  g_wqkv);
    cudaGetSymbolAddress(&pwprj,  g_wprj);
    cudaGetSymbolAddress(&pw1p,   g_w1p);
    cudaGetSymbolAddress(&pw2p,   g_w2p);

    cudaFuncSetAttribute(attn_k, cudaFuncAttributeMaxDynamicSharedMemorySize,
                         84480);

    prep_k<<<3584, 256>>>(qkv_w, proj_w, ffn_w1, ffn_w2,
                          (uint32_t*)pwqkv, (uint32_t*)pwprj,
                          (uint32_t*)pw1p, (uint32_t*)pw2p,
                          table, relidx, (uint32_t*)pbiasb);
    ln1t_k<<<dim3(32, BATCH), 256>>>(x, n1w, n1b, (uint32_t*)px1b);
    gemm_b_k<2><<<dim3(6, 128), 256>>>(
        (const uint32_t*)px1b, (const uint32_t*)pwqkv, nullptr, nullptr,
        MTOT, 768, 256, nullptr,
        (uint32_t*)pqb, (uint32_t*)pkb, (float*)pvf);
    vt_cvt_k<<<dim3(8, NHEAD, BATCH), 256>>>((const float*)pvf, (uint32_t*)pvt);
    attn_k<<<dim3(NTOK / 128, NHEAD, BATCH), 256, 84480>>>(
        (const uint32_t*)pqb, (const uint32_t*)pkb, (const uint32_t*)pvt,
        (const uint32_t*)pbiasb, (uint32_t*)pob);
    gemm_b_k<3><<<dim3(2, 128), 256>>>(
        (const uint32_t*)pob, (const uint32_t*)pwprj, proj_b, px3,
        MTOT, 256, 256, x, nullptr, nullptr, nullptr);
    ln2w_k<<<MTOT / 8, 256>>>((const float*)px3, n2w, n2b, (uint32_t*)px4b);
    gemm_b_k<0><<<dim3(8, 128), 256>>>(
        (const uint32_t*)px4b, (const uint32_t*)pw1p, ffn_b1, pffnb,
        MTOT, HID, 256, nullptr, nullptr, nullptr, nullptr);
    gemm_b_k<1><<<dim3(2, 128), 256>>>(
        (const uint32_t*)pffnb, (const uint32_t*)pw2p, ffn_b2, out,
        MTOT, 256, 1024, (const float*)px3, nullptr, nullptr, nullptr);
}